// round 17
// baseline (speedup 1.0000x reference)
#include <cuda_runtime.h>
#include <cstdint>

#define BB 64
#define TT 512
#define DD 1024
#define KK 32
#define BTK (BB*TT*KK)

// scratch (allowed: __device__ globals, no allocation)
__device__ __align__(16) float g_scratch_logits[BTK];
__device__ float g_spart[BB];
__device__ int   g_msum[BB];
__device__ int   g_done;      // starts 0; last CRF warp resets it each run

// ---------------------------------------------------------------------------
// helpers
// ---------------------------------------------------------------------------
__device__ __forceinline__ void cpa16(void* dst, const void* src) {
    unsigned s = (unsigned)__cvta_generic_to_shared(dst);
    asm volatile("cp.async.cg.shared.global [%0], [%1], 16;\n" :: "r"(s), "l"(src));
}
__device__ __forceinline__ void cpa4(void* dst, const void* src) {
    unsigned s = (unsigned)__cvta_generic_to_shared(dst);
    asm volatile("cp.async.ca.shared.global [%0], [%1], 4;\n" :: "r"(s), "l"(src));
}
__device__ __forceinline__ void cpa_commit() { asm volatile("cp.async.commit_group;\n"); }
template<int N> __device__ __forceinline__ void cpa_wait() {
    asm volatile("cp.async.wait_group %0;\n" :: "n"(N));
}

typedef unsigned long long ull;
__device__ __forceinline__ ull fma2(ull a, ull b, ull c) {
    ull d; asm("fma.rn.f32x2 %0, %1, %2, %3;" : "=l"(d) : "l"(a), "l"(b), "l"(c));
    return d;
}
__device__ __forceinline__ ull add2(ull a, ull b) {
    ull d; asm("add.rn.f32x2 %0, %1, %2;" : "=l"(d) : "l"(a), "l"(b));
    return d;
}
__device__ __forceinline__ ull pack2(float lo, float hi) {
    ull d; asm("mov.b64 %0, {%1, %2};" : "=l"(d) : "f"(lo), "f"(hi));
    return d;
}
__device__ __forceinline__ float2 unpack2(ull v) {
    float2 f; asm("mov.b64 {%0, %1}, %2;" : "=f"(f.x), "=f"(f.y) : "l"(v));
    return f;
}

// ordered smem ops (asm volatile => program-order among themselves; the
// in-order per-warp LSU makes a prior STS visible to a later LDS of the
// same convergent warp without __syncwarp)
__device__ __forceinline__ void lds2u64(ull& x, ull& y, uint32_t addr) {
    asm volatile("ld.shared.v2.u64 {%0,%1}, [%2];" : "=l"(x), "=l"(y) : "r"(addr));
}
__device__ __forceinline__ void stsf(uint32_t addr, float v) {
    asm volatile("st.shared.f32 [%0], %1;" :: "r"(addr), "f"(v));
}

__device__ __forceinline__ uint32_t tf32cvt(float x) {
    uint32_t r; asm("cvt.rna.tf32.f32 %0, %1;" : "=r"(r) : "f"(x));
    return r;
}
__device__ __forceinline__ void mma1688(
    float& c0, float& c1, float& c2, float& c3,
    uint32_t a0, uint32_t a1, uint32_t a2, uint32_t a3,
    uint32_t b0, uint32_t b1)
{
    asm volatile(
        "mma.sync.aligned.m16n8k8.row.col.f32.tf32.tf32.f32 "
        "{%0,%1,%2,%3}, {%4,%5,%6,%7}, {%8,%9}, {%0,%1,%2,%3};"
        : "+f"(c0), "+f"(c1), "+f"(c2), "+f"(c3)
        : "r"(a0), "r"(a1), "r"(a2), "r"(a3), "r"(b0), "r"(b1));
}

__device__ __forceinline__ float warpMaxPos(float v) {
    return __uint_as_float(__reduce_max_sync(0xffffffffu, __float_as_uint(v)));
}
__device__ __forceinline__ float warpSumf(float v) {
#pragma unroll
    for (int o = 16; o > 0; o >>= 1)
        v += __shfl_xor_sync(0xffffffffu, v, o);
    return v;
}
__device__ __forceinline__ int warpSumi(int v) {
#pragma unroll
    for (int o = 16; o > 0; o >>= 1)
        v += __shfl_xor_sync(0xffffffffu, v, o);
    return v;
}

// ---------------------------------------------------------------------------
// GEMM via 3xTF32 mma: logits = V @ W^T + bias. 256 threads / 8 warps,
// tile 128 rows x 32 k, 256 blocks (2/SM). D chunks of 32 (4 k8-steps),
// 3-stage cp.async, one barrier per chunk. W is staged RAW; the tf32 hi/lo
// split happens at fragment-load time (identical cvt ops to a pre-split —
// bit-identical result, no wsplit kernel, half the W smem + traffic).
// ---------------------------------------------------------------------------
#define GSTR 36

__global__ __launch_bounds__(256, 2) void gemm_kernel(
    const float* __restrict__ V, const float* __restrict__ W,
    const float* __restrict__ bias, float* __restrict__ out)
{
    __shared__ __align__(16) float Vs[3][128 * GSTR];   // 55296 B
    __shared__ __align__(16) float Ws[3][32 * GSTR];    // 13824 B

    const int tid  = threadIdx.x;
    const int w    = tid >> 5;
    const int lane = tid & 31;
    const int gid  = lane >> 2;
    const int tig  = lane & 3;
    const int rowBase = blockIdx.x * 128;
    const int wr = w * 16;

    float c[4][4];
#pragma unroll
    for (int nt = 0; nt < 4; nt++)
#pragma unroll
        for (int r = 0; r < 4; r++) c[nt][r] = 0.f;

    auto loadChunk = [&](int st, int ch) {
        const int d0 = ch * 32;
#pragma unroll
        for (int p = 0; p < 4; p++) {                 // V: 1024 float4
            int idx = p * 256 + tid;
            int r = idx >> 3, c4 = idx & 7;
            cpa16(&Vs[st][r * GSTR + c4 * 4],
                  &V[(size_t)(rowBase + r) * DD + d0 + c4 * 4]);
        }
        {                                             // W raw: 256 float4
            int k = tid >> 3, c4 = tid & 7;
            cpa16(&Ws[st][k * GSTR + c4 * 4],
                  &W[(size_t)k * DD + d0 + c4 * 4]);
        }
        cpa_commit();
    };

    loadChunk(0, 0);
    loadChunk(1, 1);

    for (int ch = 0; ch < 32; ch++) {
        cpa_wait<1>();
        __syncthreads();
        if (ch + 2 < 32) loadChunk((ch + 2) % 3, ch + 2);
        else cpa_commit();
        const float* Vst = Vs[ch % 3];
        const float* Wst = Ws[ch % 3];

#pragma unroll
        for (int k8 = 0; k8 < 4; k8++) {
            const int ab = (wr + gid) * GSTR + k8 * 8 + tig;
            float a0f = Vst[ab];
            float a1f = Vst[ab + 8 * GSTR];
            float a2f = Vst[ab + 4];
            float a3f = Vst[ab + 8 * GSTR + 4];
            uint32_t ah0 = tf32cvt(a0f), ah1 = tf32cvt(a1f);
            uint32_t ah2 = tf32cvt(a2f), ah3 = tf32cvt(a3f);
            uint32_t al0 = tf32cvt(a0f - __uint_as_float(ah0));
            uint32_t al1 = tf32cvt(a1f - __uint_as_float(ah1));
            uint32_t al2 = tf32cvt(a2f - __uint_as_float(ah2));
            uint32_t al3 = tf32cvt(a3f - __uint_as_float(ah3));

#pragma unroll
            for (int nt = 0; nt < 4; nt++) {
                const int bb = (nt * 8 + gid) * GSTR + k8 * 8 + tig;
                float bw0 = Wst[bb], bw1 = Wst[bb + 4];
                uint32_t bh0 = tf32cvt(bw0);
                uint32_t bl0 = tf32cvt(bw0 - __uint_as_float(bh0));
                uint32_t bh1 = tf32cvt(bw1);
                uint32_t bl1 = tf32cvt(bw1 - __uint_as_float(bh1));
                mma1688(c[nt][0], c[nt][1], c[nt][2], c[nt][3],
                        ah0, ah1, ah2, ah3, bh0, bh1);
                mma1688(c[nt][0], c[nt][1], c[nt][2], c[nt][3],
                        al0, al1, al2, al3, bh0, bh1);
                mma1688(c[nt][0], c[nt][1], c[nt][2], c[nt][3],
                        ah0, ah1, ah2, ah3, bl0, bl1);
            }
        }
    }

    const size_t r0 = (size_t)(rowBase + wr + gid) * KK;
    const size_t r1 = (size_t)(rowBase + wr + gid + 8) * KK;
#pragma unroll
    for (int nt = 0; nt < 4; nt++) {
        int col = nt * 8 + 2 * tig;
        float b0 = bias[col], b1 = bias[col + 1];
        out[r0 + col]     = c[nt][0] + b0;
        out[r0 + col + 1] = c[nt][1] + b1;
        out[r1 + col]     = c[nt][2] + b0;
        out[r1 + col + 1] = c[nt][3] + b1;
    }
}

// ---------------------------------------------------------------------------
// CRF forward + gold-path + fused finish. 64 blocks x 32 threads, warp =
// one batch. Raw-probability recurrence a' = (a·E)*exp(lg), renorm every 8
// steps (validated rel_err 3e-7). NO per-step __syncwarp: the warp stays
// convergent (all branches uniform) and smem STS->LDS from one warp is
// in-order; asm volatile pins compiler order. Step: 8x ld.shared.v2.u64
// (broadcast) -> 8 independent 2-deep fma2 chains -> add2 tree -> masked
// mul -> st.shared.f32.
// ---------------------------------------------------------------------------
__global__ __launch_bounds__(32) void crf_kernel(
    const float* __restrict__ L,       // logits [B,T,K] (4B aligned ok)
    const int*   __restrict__ mask,    // [B,T]
    const int*   __restrict__ targets, // [B,T]
    const float* __restrict__ trans,   // [K,K]
    const float* __restrict__ startT,  // [K]
    const float* __restrict__ endT,    // [K]
    float* __restrict__ out0, int writeLoss)
{
    __shared__ __align__(16) float Ls[2][16 * 32];   // staging, 4KB
    __shared__ __align__(16) float ash[2][32];       // ping-pong alpha

    const int b = blockIdx.x;
    const int j = threadIdx.x;
    const unsigned FULL = 0xffffffffu;

    const uint32_t ashBase =
        (uint32_t)__cvta_generic_to_shared(&ash[0][0]);

    // packed E column j: ep[p] = (exp(trans[2p][j]), exp(trans[2p+1][j]))
    ull ep[16];
#pragma unroll
    for (int p = 0; p < 16; p++) {
        float e0 = __expf(trans[(2 * p) * KK + j]);
        float e1 = __expf(trans[(2 * p + 1) * KK + j]);
        ep[p] = pack2(e0, e1);
    }

    const float* Lb = L + (size_t)b * TT * KK;
    const int*   mb = mask + (size_t)b * TT;

    unsigned mbits[16];
#pragma unroll
    for (int w = 0; w < 16; w++)
        mbits[w] = __ballot_sync(FULL, mb[w * 32 + j] != 0);

    auto loadChunk = [&](int buf, int c) {
        const float* src = Lb + (size_t)c * 512;
#pragma unroll
        for (int q = 0; q < 16; q++)
            cpa4(&Ls[buf][q * 32 + j], src + q * 32 + j);
        cpa_commit();
    };

    loadChunk(0, 0);
    loadChunk(1, 1);

    float a = 0.f, cl = 0.f;
    int pp = 0;
    const float sj = startT[j];

    for (int c = 0; c < 32; c++) {
        cpa_wait<1>();
        __syncwarp();                        // cp.async data visible to warp
        const int cb = c & 1;

        // chunk header: pull logits; steps never touch Ls after this
        float gg[16];
#pragma unroll
        for (int s = 0; s < 16; s++) gg[s] = Ls[cb][s * 32 + j];
        __syncwarp();                        // reads done before refill
        if (c + 2 < 32) loadChunk(cb, c + 2);
        else cpa_commit();

        const unsigned bits = (mbits[c >> 1] >> ((c & 1) * 16)) & 0xFFFFu;

        if (c == 0) {                        // t = 0 init (always included)
            a = __expf(sj + gg[0]);
            stsf(ashBase + 4u * j, a);
            pp = 0;
        }
        // MUFU burst off the serial chain
#pragma unroll
        for (int s = 0; s < 16; s++) gg[s] = __expf(gg[s]);

#pragma unroll
        for (int s = 0; s < 16; s++) {
            if (c == 0 && s == 0) continue;
            const uint32_t rb = ashBase + (pp ? 128u : 0u);
            const uint32_t wb = ashBase + (pp ? 0u : 128u);
            ull q[16];
            lds2u64(q[0],  q[1],  rb);
            lds2u64(q[2],  q[3],  rb + 16);
            lds2u64(q[4],  q[5],  rb + 32);
            lds2u64(q[6],  q[7],  rb + 48);
            lds2u64(q[8],  q[9],  rb + 64);
            lds2u64(q[10], q[11], rb + 80);
            lds2u64(q[12], q[13], rb + 96);
            lds2u64(q[14], q[15], rb + 112);
            ull p0 = fma2(q[1],  ep[1],  fma2(q[0],  ep[0],  0ull));
            ull p1 = fma2(q[3],  ep[3],  fma2(q[2],  ep[2],  0ull));
            ull p2 = fma2(q[5],  ep[5],  fma2(q[4],  ep[4],  0ull));
            ull p3 = fma2(q[7],  ep[7],  fma2(q[6],  ep[6],  0ull));
            ull p4 = fma2(q[9],  ep[9],  fma2(q[8],  ep[8],  0ull));
            ull p5 = fma2(q[11], ep[11], fma2(q[10], ep[10], 0ull));
            ull p6 = fma2(q[13], ep[13], fma2(q[12], ep[12], 0ull));
            ull p7 = fma2(q[15], ep[15], fma2(q[14], ep[14], 0ull));
            ull t0 = add2(p0, p1), t1 = add2(p2, p3);
            ull t2 = add2(p4, p5), t3 = add2(p6, p7);
            ull v  = add2(add2(t0, t1), add2(t2, t3));
            float2 f = unpack2(v);
            float dot = f.x + f.y;
            if ((bits >> s) & 1u) a = dot * gg[s];
            if ((s & 7) == 7) {              // renorm (semantically neutral)
                float Mx = warpMaxPos(a);
                a = __fdividef(a, Mx);
                cl += __logf(Mx);
            }
            stsf(wb + 4u * j, a);
            pp ^= 1;
        }
    }

    // partition = cl + log(sum_j a_j * exp(end_j))
    float S = warpSumf(a * __expf(endT[j]));
    float partition = cl + __logf(S);

    // ---- gold path score ----
    float emit_s = 0.f, trans_s = 0.f;
    int msum = 0;
    for (int t = j; t < TT; t += 32) {
        int tg = targets[(size_t)b * TT + t];
        int mk = mb[t];
        emit_s += Lb[(size_t)t * KK + tg] * (float)mk;
        if (t >= 1) {
            int tgp = targets[(size_t)b * TT + t - 1];
            trans_s += trans[tgp * KK + tg] * (float)mk;
        }
        msum += mk;
    }
    emit_s  = warpSumf(emit_s);
    trans_s = warpSumf(trans_s);
    msum    = warpSumi(msum);

    if (j == 0) {
        int last = msum - 1;
        int t0 = targets[(size_t)b * TT];
        int tl = targets[(size_t)b * TT + last];
        float score = startT[t0] + emit_s + trans_s + endT[tl];
        g_spart[b] = score - partition;
        g_msum[b]  = msum;
    }

    // ---- last finished warp computes the loss, then resets the counter ----
    __threadfence();
    int lastw = 0;
    if (j == 0) lastw = (atomicAdd(&g_done, 1) == BB - 1) ? 1 : 0;
    lastw = __shfl_sync(FULL, lastw, 0);
    if (lastw) {
        __threadfence();
        float sp = g_spart[j] + g_spart[j + 32];
        int   ms = g_msum[j]  + g_msum[j + 32];
        sp = warpSumf(sp);
        ms = warpSumi(ms);
        if (j == 0) {
            if (writeLoss) out0[0] = -sp / (float)ms;
            g_done = 0;                      // replay-safe reset
        }
    }
}

// ---------------------------------------------------------------------------
extern "C" void kernel_launch(void* const* d_in, const int* in_sizes, int n_in,
                              void* d_out, int out_size)
{
    const float* V       = (const float*)d_in[0];
    const int*   mask    = (const int*)  d_in[1];
    const int*   targets = (const int*)  d_in[2];
    const float* W       = (const float*)d_in[3];
    const float* bias    = (const float*)d_in[4];
    const float* trans   = (const float*)d_in[5];
    const float* startT  = (const float*)d_in[6];
    const float* endT    = (const float*)d_in[7];
    float* out = (float*)d_out;

    void* p = nullptr;
    cudaGetSymbolAddress(&p, g_scratch_logits);
    float* scratch = (float*)p;

    const int loff = out_size - BTK;   // (loss, logits) concat
    float* outLogits = (loff >= 0) ? (out + loff) : scratch;

    gemm_kernel<<<(BB * TT) / 128, 256>>>(V, W, bias, outLogits);
    crf_kernel<<<BB, 32>>>(outLogits, mask, targets, trans, startT, endT,
                           out, (loff >= 1) ? 1 : 0);
}